// round 6
// baseline (speedup 1.0000x reference)
#include <cuda_runtime.h>
#include <cuda_bf16.h>
#include <cstdint>

// Problem constants
#define BATCH 8
#define NQ    2048
#define NS    4096
#define DIM   512

// Tiling
#define BM 128
#define BN 256
#define BK 64
#define NCHUNK ((NS / BN) * (DIM / BK))   // 16 stiles * 8 kchunks = 128
#define NBUF 3

#define A_BYTES    (BM * DIM * 2)         // 131072 = 8 chunks of 16KB (64 cols each)
#define BBUF_BYTES (BN * BK * 2)          // 32768  = one swizzled region (256 rows x 128B)
#define RM_OFF     (A_BYTES + NBUF * BBUF_BYTES)   // 229376
#define SMEM_TOTAL (RM_OFF + BM * 4)               // 229888

// Device scratch
__device__ __nv_bfloat16 g_qn[(size_t)BATCH * NQ * DIM];
__device__ __nv_bfloat16 g_sn[(size_t)BATCH * NS * DIM];
__device__ float         g_maxdot[(size_t)BATCH * NQ];

// ---------------------------------------------------------------------------
// helpers
// ---------------------------------------------------------------------------
__device__ __forceinline__ uint32_t swz(uint32_t x) {   // SW128: bits[6:4] ^= bits[9:7]
    return x ^ ((x >> 3) & 0x70);
}
__device__ __forceinline__ void cp_async16(uint32_t saddr, const void* gptr) {
    asm volatile("cp.async.cg.shared.global [%0], [%1], 16;\n" :: "r"(saddr), "l"(gptr));
}
__device__ __forceinline__ void cp_commit() {
    asm volatile("cp.async.commit_group;\n" ::: "memory");
}
template <int N>
__device__ __forceinline__ void cp_wait() {
    asm volatile("cp.async.wait_group %0;\n" :: "n"(N) : "memory");
}
__device__ __forceinline__ unsigned fkey(float f) {
    unsigned u = __float_as_uint(f);
    return (u & 0x80000000u) ? ~u : (u | 0x80000000u);
}
__device__ __forceinline__ float funkey(unsigned k) {
    unsigned u = (k & 0x80000000u) ? (k ^ 0x80000000u) : ~k;
    return __uint_as_float(u);
}

// ---------------------------------------------------------------------------
// Normalize: one warp per row of 512 fp32 -> bf16
// ---------------------------------------------------------------------------
__device__ __forceinline__ void normalize_row(const float* __restrict__ rinF,
                                              __nv_bfloat16* __restrict__ orow, int lane)
{
    const float4* rin = reinterpret_cast<const float4*>(rinF);
    float4 v[4];
    float s = 0.f;
#pragma unroll
    for (int j = 0; j < 4; j++) {
        v[j] = rin[j * 32 + lane];
        s += v[j].x * v[j].x + v[j].y * v[j].y + v[j].z * v[j].z + v[j].w * v[j].w;
    }
#pragma unroll
    for (int o = 16; o > 0; o >>= 1) s += __shfl_xor_sync(0xFFFFFFFFu, s, o);
    float inv = 1.0f / fmaxf(sqrtf(s), 1e-12f);
#pragma unroll
    for (int j = 0; j < 4; j++) {
        __nv_bfloat162 h0 = __floats2bfloat162_rn(v[j].x * inv, v[j].y * inv);
        __nv_bfloat162 h1 = __floats2bfloat162_rn(v[j].z * inv, v[j].w * inv);
        uint2 pk;
        pk.x = *reinterpret_cast<unsigned*>(&h0);
        pk.y = *reinterpret_cast<unsigned*>(&h1);
        *reinterpret_cast<uint2*>(orow + (size_t)(j * 32 + lane) * 4) = pk;
    }
}

__global__ void normalize_all_kernel(const float* __restrict__ q,
                                     const float* __restrict__ s)
{
    int row = blockIdx.x * (blockDim.x >> 5) + (threadIdx.x >> 5);
    int lane = threadIdx.x & 31;
    const int nq = BATCH * NQ;
    const int ntot = nq + BATCH * NS;
    if (row >= ntot) return;
    if (row < nq)
        normalize_row(q + (size_t)row * DIM, g_qn + (size_t)row * DIM, lane);
    else {
        int r = row - nq;
        normalize_row(s + (size_t)r * DIM, g_sn + (size_t)r * DIM, lane);
    }
}

// ---------------------------------------------------------------------------
// B chunk fill: chunk ci = st*8 + kc covers support rows [st*256, +256),
// k-cols [kc*64, +64). 2048 x 16B segments, 8 per thread (256 threads).
// Swizzled region: 256 rows x 128B.
// ---------------------------------------------------------------------------
__device__ __forceinline__ void fill_b_chunk(uint32_t smem_u32,
                                             const __nv_bfloat16* __restrict__ gB,
                                             int ci, int tid)
{
    const int st = ci >> 3;
    const int kc = ci & 7;
    const uint32_t bb = A_BYTES + (uint32_t)(ci % NBUF) * BBUF_BYTES;
#pragma unroll
    for (int i = 0; i < 8; i++) {
        int idx = tid + i * 256;         // 0..2047
        int r = idx >> 3;                // 8 segs per row (64 cols)
        int s8 = idx & 7;
        const void* src = gB + (size_t)(st * BN + r) * DIM + kc * BK + s8 * 8;
        cp_async16(smem_u32 + bb + swz((uint32_t)(r * 128 + s8 * 16)), src);
    }
    cp_commit();
}

// ---------------------------------------------------------------------------
// GEMM-max: one block per (batch, q-tile). A resident (swizzled), B 3-buffer
// depth-2 cp.async pipeline, one __syncthreads per 64-wide k-chunk.
// 8 warps, warp tile 64x64 (2x4 warp grid), mma.sync m16n8k16 bf16.
// Per chunk/warp: 128 MMA vs 32 ldmatrix.x4.
// ---------------------------------------------------------------------------
__global__ __launch_bounds__(256, 1) void gemm_max_kernel()
{
    extern __shared__ char smem[];
    unsigned* rowmaxU = reinterpret_cast<unsigned*>(smem + RM_OFF);
    const uint32_t smem_u32 = (uint32_t)__cvta_generic_to_shared(smem);

    const int b   = blockIdx.x >> 4;
    const int qt  = blockIdx.x & 15;
    const int tid = threadIdx.x;
    const int lane = tid & 31;
    const int wid  = tid >> 5;
    const int wm = (wid >> 2) * 64;      // 2 m-warps
    const int wn = (wid & 3) * 64;       // 4 n-warps

    if (tid < BM) rowmaxU[tid] = 0u;

    // ---- A tile: 128 x 512 bf16, 8 swizzled 64-col chunks ----
    const __nv_bfloat16* gA = g_qn + (size_t)(b * NQ + qt * BM) * DIM;
#pragma unroll
    for (int i = 0; i < 32; i++) {
        int idx = tid + i * 256;         // 0..8191 16B segs
        int r = idx >> 6;                // 64 segs per row
        int rest = idx & 63;
        int ch = rest >> 3;
        int s8 = rest & 7;
        const void* src = gA + (size_t)r * DIM + ch * 64 + s8 * 8;
        cp_async16(smem_u32 + ch * 16384 + swz((uint32_t)(r * 128 + s8 * 16)), src);
    }
    cp_commit();

    const __nv_bfloat16* gB = g_sn + (size_t)b * NS * DIM;

    // prologue: chunks 0, 1
    fill_b_chunk(smem_u32, gB, 0, tid);
    fill_b_chunk(smem_u32, gB, 1, tid);

    float C[2][8][4];
#pragma unroll
    for (int mi = 0; mi < 2; mi++)
#pragma unroll
        for (int ni = 0; ni < 8; ni++)
#pragma unroll
            for (int e = 0; e < 4; e++) C[mi][ni][e] = 0.f;
    float C2[2][8][4];
#pragma unroll
    for (int mi = 0; mi < 2; mi++)
#pragma unroll
        for (int ni = 0; ni < 8; ni++)
#pragma unroll
            for (int e = 0; e < 4; e++) C2[mi][ni][e] = 0.f;

    float rmax[4][2];
#pragma unroll
    for (int mi = 0; mi < 4; mi++) { rmax[mi][0] = -1e30f; rmax[mi][1] = -1e30f; }

    for (int ci = 0; ci < NCHUNK; ci++) {
        if (ci < NCHUNK - 1) cp_wait<1>(); else cp_wait<0>();
        __syncthreads();
        if (ci + 2 < NCHUNK) fill_b_chunk(smem_u32, gB, ci + 2, tid);

        const int kc = ci & 7;           // == A chunk index for this k-range
        const uint32_t bb = A_BYTES + (uint32_t)(ci % NBUF) * BBUF_BYTES;

#pragma unroll
        for (int ksp = 0; ksp < 2; ksp++) {
            // B x4 fragments: 2 ksteps per instruction, 8 n-tiles
            unsigned bfr[8][4];
            {
                const uint32_t kb = (uint32_t)(ksp * 64
                                  + ((lane >> 3) & 1) * 16 + (lane >> 4) * 32);
#pragma unroll
                for (int ni = 0; ni < 8; ni++) {
                    int n = wn + ni * 8 + (lane & 7);
                    uint32_t addr = smem_u32 + bb + swz((uint32_t)(n * 128) + kb);
                    asm volatile("ldmatrix.sync.aligned.m8n8.x4.shared.b16 {%0,%1,%2,%3}, [%4];"
                                 : "=r"(bfr[ni][0]), "=r"(bfr[ni][1]),
                                   "=r"(bfr[ni][2]), "=r"(bfr[ni][3])
                                 : "r"(addr));
                }
            }
#pragma unroll
            for (int h = 0; h < 2; h++) {
                const int ks = ksp * 2 + h;
                const uint32_t kb = (uint32_t)(ks * 32 + (lane >> 4) * 16);
                unsigned afr[2][4][2];   // [mi][frag pair][..] -> actually 2 m-tiles x4
                unsigned af[2][4];
#pragma unroll
                for (int mi = 0; mi < 2; mi++) {
                    int r = wm + mi * 32 + (lane & 15) + ((lane >> 4) ? 0 : 0);
                    // two 16-row tiles per 32: load both with separate x4
                    (void)afr;
                    int r0 = wm + mi * 32 + (lane & 15);
                    uint32_t addr = smem_u32 + kc * 16384
                                  + swz((uint32_t)(r0 * 128) + kb);
                    asm volatile("ldmatrix.sync.aligned.m8n8.x4.shared.b16 {%0,%1,%2,%3}, [%4];"
                                 : "=r"(af[mi][0]), "=r"(af[mi][1]),
                                   "=r"(af[mi][2]), "=r"(af[mi][3])
                                 : "r"(addr));
                    (void)r;
                }
                unsigned af2[2][4];
#pragma unroll
                for (int mi = 0; mi < 2; mi++) {
                    int r0 = wm + mi * 32 + 16 + (lane & 15);
                    uint32_t addr = smem_u32 + kc * 16384
                                  + swz((uint32_t)(r0 * 128) + kb);
                    asm volatile("ldmatrix.sync.aligned.m8n8.x4.shared.b16 {%0,%1,%2,%3}, [%4];"
                                 : "=r"(af2[mi][0]), "=r"(af2[mi][1]),
                                   "=r"(af2[mi][2]), "=r"(af2[mi][3])
                                 : "r"(addr));
                }
#pragma unroll
                for (int mi = 0; mi < 2; mi++)
#pragma unroll
                    for (int ni = 0; ni < 8; ni++) {
                        asm volatile(
                            "mma.sync.aligned.m16n8k16.row.col.f32.bf16.bf16.f32 "
                            "{%0,%1,%2,%3}, {%4,%5,%6,%7}, {%8,%9}, {%0,%1,%2,%3};"
                            : "+f"(C[mi][ni][0]), "+f"(C[mi][ni][1]),
                              "+f"(C[mi][ni][2]), "+f"(C[mi][ni][3])
                            : "r"(af[mi][0]), "r"(af[mi][1]),
                              "r"(af[mi][2]), "r"(af[mi][3]),
                              "r"(bfr[ni][2 * h]), "r"(bfr[ni][2 * h + 1]));
                        asm volatile(
                            "mma.sync.aligned.m16n8k16.row.col.f32.bf16.bf16.f32 "
                            "{%0,%1,%2,%3}, {%4,%5,%6,%7}, {%8,%9}, {%0,%1,%2,%3};"
                            : "+f"(C2[mi][ni][0]), "+f"(C2[mi][ni][1]),
                              "+f"(C2[mi][ni][2]), "+f"(C2[mi][ni][3])
                            : "r"(af2[mi][0]), "r"(af2[mi][1]),
                              "r"(af2[mi][2]), "r"(af2[mi][3]),
                              "r"(bfr[ni][2 * h]), "r"(bfr[ni][2 * h + 1]));
                    }
            }
        }

        if (kc == 7) {   // end of s-tile: fold into running row max, reset C
#pragma unroll
            for (int mi = 0; mi < 2; mi++) {
                float m0 = rmax[2 * mi][0], m1 = rmax[2 * mi][1];
                float n0 = rmax[2 * mi + 1][0], n1 = rmax[2 * mi + 1][1];
#pragma unroll
                for (int ni = 0; ni < 8; ni++) {
                    m0 = fmaxf(m0, fmaxf(C[mi][ni][0], C[mi][ni][1]));
                    m1 = fmaxf(m1, fmaxf(C[mi][ni][2], C[mi][ni][3]));
                    n0 = fmaxf(n0, fmaxf(C2[mi][ni][0], C2[mi][ni][1]));
                    n1 = fmaxf(n1, fmaxf(C2[mi][ni][2], C2[mi][ni][3]));
                    C[mi][ni][0] = 0.f; C[mi][ni][1] = 0.f;
                    C[mi][ni][2] = 0.f; C[mi][ni][3] = 0.f;
                    C2[mi][ni][0] = 0.f; C2[mi][ni][1] = 0.f;
                    C2[mi][ni][2] = 0.f; C2[mi][ni][3] = 0.f;
                }
                rmax[2 * mi][0] = m0; rmax[2 * mi][1] = m1;
                rmax[2 * mi + 1][0] = n0; rmax[2 * mi + 1][1] = n1;
            }
        }
    }

    // epilogue: rmax[t] covers rows wm + t*16 (t in 0..3), lane row (lane>>2)+g*8
#pragma unroll
    for (int t = 0; t < 4; t++) {
#pragma unroll
        for (int g = 0; g < 2; g++) {
            int row = wm + t * 16 + (lane >> 2) + g * 8;
            atomicMax(&rowmaxU[row], fkey(rmax[t][g]));
        }
    }
    __syncthreads();
    if (tid < BM)
        g_maxdot[(size_t)b * NQ + qt * BM + tid] = funkey(rowmaxU[tid]);
}

// ---------------------------------------------------------------------------
// Finalize: out[b] = mean over q of (1 - maxdot)
// ---------------------------------------------------------------------------
__global__ void finalize_kernel(float* __restrict__ out)
{
    __shared__ float red[256];
    int b = blockIdx.x;
    float s = 0.f;
    for (int i = threadIdx.x; i < NQ; i += 256)
        s += 1.0f - g_maxdot[(size_t)b * NQ + i];
    red[threadIdx.x] = s;
    __syncthreads();
#pragma unroll
    for (int o = 128; o > 0; o >>= 1) {
        if (threadIdx.x < o) red[threadIdx.x] += red[threadIdx.x + o];
        __syncthreads();
    }
    if (threadIdx.x == 0) out[b] = red[0] * (1.0f / NQ);
}

// ---------------------------------------------------------------------------
extern "C" void kernel_launch(void* const* d_in, const int* in_sizes, int n_in,
                              void* d_out, int out_size)
{
    const float* q = (const float*)d_in[0];
    const float* s = (const float*)d_in[1];
    float* out = (float*)d_out;

    cudaFuncSetAttribute(gemm_max_kernel,
                         cudaFuncAttributeMaxDynamicSharedMemorySize, SMEM_TOTAL);

    const int nrows = BATCH * (NQ + NS);
    normalize_all_kernel<<<(nrows + 7) / 8, 256>>>(q, s);
    gemm_max_kernel<<<BATCH * (NQ / BM), 256, SMEM_TOTAL>>>();
    finalize_kernel<<<BATCH, 256>>>(out);
}